// round 5
// baseline (speedup 1.0000x reference)
#include <cuda_runtime.h>
#include <cuda_bf16.h>
#include <math.h>

#define N_NODES 100864
#define N_EDGES 1613824
#define N_GRAPHS 512
#define IN_C 384
#define HID 128
#define OUT_C 2

// ---------------- scratch (static __device__, no allocs) ----------------
__device__ int   g_cnt[N_NODES];
__device__ int   g_rowptr[N_NODES + 1];
__device__ int   g_fill[N_NODES];
__device__ int   g_col[N_EDGES];
__device__ __align__(16) float g_dinv[N_NODES];
__device__ __align__(16) float g_bufA[(size_t)N_NODES * HID];  // GEMM output
__device__ __align__(16) float g_bufB[(size_t)N_NODES * HID];  // aggregation output
__device__ __align__(16) float g_pool[N_GRAPHS * HID];
__device__ __align__(16) float g_cntg[N_GRAPHS];

// ---------------- init: zero counters / pool ----------------
__global__ void init_kernel() {
    int i = blockIdx.x * blockDim.x + threadIdx.x;
    if (i < N_NODES) g_cnt[i] = 0;
    if (i < N_GRAPHS * HID) g_pool[i] = 0.0f;
    if (i < N_GRAPHS) g_cntg[i] = 0.0f;
}

// ---------------- degree count (dst side) ----------------
__global__ void count_kernel(const int* __restrict__ edge) {
    int e = blockIdx.x * blockDim.x + threadIdx.x;
    if (e >= N_EDGES) return;
    unsigned dst = (unsigned)edge[N_EDGES + e];
    if (dst >= N_NODES) dst = 0;      // safety clamp (should never fire)
    atomicAdd(&g_cnt[dst], 1);
}

// ---------------- single-block scan: rowptr, fill, dinv ----------------
__global__ void scan_kernel() {
    __shared__ int sh[1024];
    const int n = N_NODES;
    const int C = (n + 1023) / 1024;
    int t = threadIdx.x;
    int beg = t * C;
    int end = beg + C; if (end > n) end = n;
    int s = 0;
    for (int i = beg; i < end; i++) s += g_cnt[i];
    sh[t] = s;
    __syncthreads();
    for (int off = 1; off < 1024; off <<= 1) {
        int v = (t >= off) ? sh[t - off] : 0;
        __syncthreads();
        sh[t] += v;
        __syncthreads();
    }
    int run = (t == 0) ? 0 : sh[t - 1];
    for (int i = beg; i < end; i++) {
        int c = g_cnt[i];
        g_rowptr[i] = run;
        g_fill[i]   = run;
        g_dinv[i]   = rsqrtf((float)c + 1.0f);  // +1 self-loop
        run += c;
    }
    if (t == 1023) g_rowptr[n] = run;
}

// ---------------- CSR fill ----------------
__global__ void fill_kernel(const int* __restrict__ edge) {
    int e = blockIdx.x * blockDim.x + threadIdx.x;
    if (e >= N_EDGES) return;
    unsigned src = (unsigned)edge[e];
    unsigned dst = (unsigned)edge[N_EDGES + e];
    if (src >= N_NODES) src = 0;      // safety clamp
    if (dst >= N_NODES) dst = 0;
    int p = atomicAdd(&g_fill[dst], 1);
    g_col[p] = (int)src;
}

// ---------------- SGEMM body: C[M,128] = A[M,K] @ B[K,128] (BM=BN=128, BK=8) --
__device__ __forceinline__ void sgemm_body(const float* __restrict__ A,
                                           const float* __restrict__ B,
                                           float* __restrict__ C, int K) {
    __shared__ float As[8][128];
    __shared__ float Bs[8][128];
    int tid = threadIdx.x;            // 256 threads
    int tx = tid & 15;                // 0..15 -> n microtile
    int ty = tid >> 4;                // 0..15 -> m microtile
    int rowBase = blockIdx.y * 128;

    int aRow = tid >> 1;              // 0..127
    int aCol = (tid & 1) * 4;         // 0 or 4
    int bRow = tid >> 5;              // 0..7
    int bCol = (tid & 31) * 4;        // 0..124

    float acc[8][8];
    #pragma unroll
    for (int i = 0; i < 8; i++)
        #pragma unroll
        for (int j = 0; j < 8; j++) acc[i][j] = 0.0f;

    for (int k0 = 0; k0 < K; k0 += 8) {
        float4 a = *(const float4*)&A[(size_t)(rowBase + aRow) * K + k0 + aCol];
        As[aCol + 0][aRow] = a.x;
        As[aCol + 1][aRow] = a.y;
        As[aCol + 2][aRow] = a.z;
        As[aCol + 3][aRow] = a.w;
        *(float4*)&Bs[bRow][bCol] = *(const float4*)&B[(size_t)(k0 + bRow) * 128 + bCol];
        __syncthreads();
        #pragma unroll
        for (int kk = 0; kk < 8; kk++) {
            float ra[8], rb[8];
            *(float4*)&ra[0] = *(const float4*)&As[kk][ty * 8];
            *(float4*)&ra[4] = *(const float4*)&As[kk][ty * 8 + 4];
            *(float4*)&rb[0] = *(const float4*)&Bs[kk][tx * 8];
            *(float4*)&rb[4] = *(const float4*)&Bs[kk][tx * 8 + 4];
            #pragma unroll
            for (int i = 0; i < 8; i++)
                #pragma unroll
                for (int j = 0; j < 8; j++) acc[i][j] += ra[i] * rb[j];
        }
        __syncthreads();
    }
    #pragma unroll
    for (int i = 0; i < 8; i++) {
        size_t r = (size_t)(rowBase + ty * 8 + i) * 128 + tx * 8;
        *(float4*)&C[r]     = make_float4(acc[i][0], acc[i][1], acc[i][2], acc[i][3]);
        *(float4*)&C[r + 4] = make_float4(acc[i][4], acc[i][5], acc[i][6], acc[i][7]);
    }
}

// wrappers: scratch buffers resolved in DEVICE code (no host symbol lookups)
__global__ __launch_bounds__(256, 2)
void sgemm1_kernel(const float* __restrict__ x, const float* __restrict__ W1) {
    sgemm_body(x, W1, g_bufA, IN_C);
}
__global__ __launch_bounds__(256, 2)
void sgemm2_kernel(const float* __restrict__ W2) {
    sgemm_body(g_bufB, W2, g_bufA, HID);
}

// ---------------- aggregation: pull-mode, 1 warp per dst node --------------
// g_bufB[v] = relu( dinv[v]*( sum_{s in N(v)} dinv[s]*g_bufA[s] + dinv[v]*g_bufA[v] ) + b )
__global__ void agg_kernel(const float* __restrict__ bias) {
    int w = (blockIdx.x * blockDim.x + threadIdx.x) >> 5;
    int lane = threadIdx.x & 31;
    if (w >= N_NODES) return;
    const float* __restrict__ h = g_bufA;
    float dv = g_dinv[w];
    float4 sv = *(const float4*)(h + (size_t)w * HID + lane * 4);
    float4 acc = make_float4(dv * sv.x, dv * sv.y, dv * sv.z, dv * sv.w);
    int beg = g_rowptr[w], end = g_rowptr[w + 1];
    for (int e = beg; e < end; e++) {
        int s = g_col[e];
        float ws = g_dinv[s];
        float4 v = *(const float4*)(h + (size_t)s * HID + lane * 4);
        acc.x += ws * v.x; acc.y += ws * v.y;
        acc.z += ws * v.z; acc.w += ws * v.w;
    }
    float4 b = *(const float4*)(bias + lane * 4);
    float4 o;
    o.x = fmaxf(dv * acc.x + b.x, 0.0f);
    o.y = fmaxf(dv * acc.y + b.y, 0.0f);
    o.z = fmaxf(dv * acc.z + b.z, 0.0f);
    o.w = fmaxf(dv * acc.w + b.w, 0.0f);
    *(float4*)(g_bufB + (size_t)w * HID + lane * 4) = o;
}

// ---------------- global mean pool (atomic accumulate from g_bufB) ---------
__global__ void pool_kernel(const int* __restrict__ bids) {
    int w = (blockIdx.x * blockDim.x + threadIdx.x) >> 5;
    int lane = threadIdx.x & 31;
    if (w >= N_NODES) return;
    unsigned g = (unsigned)bids[w];
    if (g >= N_GRAPHS) g = 0;         // safety clamp
    float4 v = *(const float4*)(g_bufB + (size_t)w * HID + lane * 4);
    float* p = &g_pool[g * HID + lane * 4];
    atomicAdd(p + 0, v.x);
    atomicAdd(p + 1, v.y);
    atomicAdd(p + 2, v.z);
    atomicAdd(p + 3, v.w);
    if (lane == 0) atomicAdd(&g_cntg[g], 1.0f);
}

// ---------------- final linear head: 1 warp per graph ----------------------
__global__ void final_kernel(const float* __restrict__ Wlin,
                             const float* __restrict__ blin,
                             float* __restrict__ out) {
    int g = (blockIdx.x * blockDim.x + threadIdx.x) >> 5;
    int lane = threadIdx.x & 31;
    if (g >= N_GRAPHS) return;
    float inv = 1.0f / fmaxf(g_cntg[g], 1.0f);
    float4 p = *(const float4*)(&g_pool[g * HID + lane * 4]);
    p.x *= inv; p.y *= inv; p.z *= inv; p.w *= inv;
    int c = lane * 4;
    float s0 = p.x * Wlin[c * 2]       + p.y * Wlin[(c + 1) * 2]
             + p.z * Wlin[(c + 2) * 2] + p.w * Wlin[(c + 3) * 2];
    float s1 = p.x * Wlin[c * 2 + 1]       + p.y * Wlin[(c + 1) * 2 + 1]
             + p.z * Wlin[(c + 2) * 2 + 1] + p.w * Wlin[(c + 3) * 2 + 1];
    #pragma unroll
    for (int off = 16; off > 0; off >>= 1) {
        s0 += __shfl_xor_sync(0xFFFFFFFF, s0, off);
        s1 += __shfl_xor_sync(0xFFFFFFFF, s1, off);
    }
    if (lane == 0) {
        out[g * 2 + 0] = s0 + blin[0];
        out[g * 2 + 1] = s1 + blin[1];
    }
}

// ---------------- launch ----------------------------------------------------
extern "C" void kernel_launch(void* const* d_in, const int* in_sizes, int n_in,
                              void* d_out, int out_size) {
    const float* x    = (const float*)d_in[0];
    const int*   edge = (const int*)d_in[1];    // int32 (JAX default, x64 off)
    const int*   bids = (const int*)d_in[2];    // int32
    const float* W1   = (const float*)d_in[3];
    const float* b1   = (const float*)d_in[4];
    const float* W2   = (const float*)d_in[5];
    const float* b2   = (const float*)d_in[6];
    const float* Wlin = (const float*)d_in[7];
    const float* blin = (const float*)d_in[8];
    float*       out  = (float*)d_out;

    // graph structure (rebuilt every call — deterministic, graph-capturable)
    init_kernel<<<(N_NODES + 255) / 256, 256>>>();
    count_kernel<<<(N_EDGES + 255) / 256, 256>>>(edge);
    scan_kernel<<<1, 1024>>>();
    fill_kernel<<<(N_EDGES + 255) / 256, 256>>>(edge);

    dim3 ggrid(1, N_NODES / 128);   // 100864 = 788 * 128, no tails
    int aggBlocks = (N_NODES * 32 + 255) / 256;

    // layer 1
    sgemm1_kernel<<<ggrid, 256>>>(x, W1);
    agg_kernel<<<aggBlocks, 256>>>(b1);
    // layer 2
    sgemm2_kernel<<<ggrid, 256>>>(W2);
    agg_kernel<<<aggBlocks, 256>>>(b2);
    // pool + head
    pool_kernel<<<aggBlocks, 256>>>(bids);
    final_kernel<<<(N_GRAPHS * 32 + 255) / 256, 256>>>(Wlin, blin, out);
}

// round 6
// speedup vs baseline: 1.1178x; 1.1178x over previous
#include <cuda_runtime.h>
#include <cuda_bf16.h>
#include <math.h>

#define N_NODES 100864
#define N_EDGES 1613824
#define N_GRAPHS 512
#define IN_C 384
#define HID 128
#define OUT_C 2

// ---------------- scratch (static __device__, no allocs) ----------------
__device__ int   g_cnt[N_NODES];
__device__ int   g_rowptr[N_NODES + 1];
__device__ int   g_fill[N_NODES];
__device__ int   g_col[N_EDGES];
__device__ __align__(16) float g_dinv[N_NODES];
__device__ __align__(16) float g_bufA[(size_t)N_NODES * HID];  // GEMM output
__device__ __align__(16) float g_bufB[(size_t)N_NODES * HID];  // aggregation output
__device__ __align__(16) float g_pool[N_GRAPHS * HID];
__device__ __align__(16) float g_cntg[N_GRAPHS];

// ---------------- init: zero counters / pool ----------------
__global__ void init_kernel() {
    int i = blockIdx.x * blockDim.x + threadIdx.x;
    if (i < N_NODES) g_cnt[i] = 0;
    if (i < N_GRAPHS * HID) g_pool[i] = 0.0f;
    if (i < N_GRAPHS) g_cntg[i] = 0.0f;
}

// ---------------- degree count (dst side) ----------------
__global__ void count_kernel(const int* __restrict__ edge) {
    int e = blockIdx.x * blockDim.x + threadIdx.x;
    if (e >= N_EDGES) return;
    unsigned dst = (unsigned)edge[N_EDGES + e];
    if (dst >= N_NODES) dst = 0;
    atomicAdd(&g_cnt[dst], 1);
}

// ---------------- single-block scan: rowptr, fill, dinv ----------------
__global__ void scan_kernel() {
    __shared__ int sh[1024];
    const int n = N_NODES;
    const int C = (n + 1023) / 1024;
    int t = threadIdx.x;
    int beg = t * C;
    int end = beg + C; if (end > n) end = n;
    int s = 0;
    for (int i = beg; i < end; i++) s += g_cnt[i];
    sh[t] = s;
    __syncthreads();
    for (int off = 1; off < 1024; off <<= 1) {
        int v = (t >= off) ? sh[t - off] : 0;
        __syncthreads();
        sh[t] += v;
        __syncthreads();
    }
    int run = (t == 0) ? 0 : sh[t - 1];
    for (int i = beg; i < end; i++) {
        int c = g_cnt[i];
        g_rowptr[i] = run;
        g_fill[i]   = run;
        g_dinv[i]   = rsqrtf((float)c + 1.0f);  // +1 self-loop
        run += c;
    }
    if (t == 1023) g_rowptr[n] = run;
}

// ---------------- CSR fill ----------------
__global__ void fill_kernel(const int* __restrict__ edge) {
    int e = blockIdx.x * blockDim.x + threadIdx.x;
    if (e >= N_EDGES) return;
    unsigned src = (unsigned)edge[e];
    unsigned dst = (unsigned)edge[N_EDGES + e];
    if (src >= N_NODES) src = 0;
    if (dst >= N_NODES) dst = 0;
    int p = atomicAdd(&g_fill[dst], 1);
    g_col[p] = (int)src;
}

// ---------------- tf32 helpers ----------------
__device__ __forceinline__ void split2(float x, unsigned& hi, unsigned& lo) {
    unsigned h; asm("cvt.rna.tf32.f32 %0, %1;" : "=r"(h) : "f"(x));
    float hf = __uint_as_float(h);
    unsigned l; asm("cvt.rna.tf32.f32 %0, %1;" : "=r"(l) : "f"(x - hf));
    hi = h; lo = l;
}
__device__ __forceinline__ void mma8(float* d, const unsigned* a, const unsigned* b) {
    asm("mma.sync.aligned.m16n8k8.row.col.f32.tf32.tf32.f32 "
        "{%0,%1,%2,%3},{%4,%5,%6,%7},{%8,%9},{%0,%1,%2,%3};"
        : "+f"(d[0]), "+f"(d[1]), "+f"(d[2]), "+f"(d[3])
        : "r"(a[0]), "r"(a[1]), "r"(a[2]), "r"(a[3]), "r"(b[0]), "r"(b[1]));
}

// ---- tensor-core GEMM: C[M,128] = A[M,K] @ B[K,128], 3xTF32 (fp32 accuracy) --
// block tile 128x128, BK=32, 8 warps (4 M x 2 N), warp tile 32x64 (2x8 m16n8k8)
template<int K>
__device__ __forceinline__ void mma_gemm_body(const float* __restrict__ A,
                                              const float* __restrict__ B,
                                              float* __restrict__ C) {
    __shared__ float As[32][136];   // [k][m], padded: +136 -> 8-bank step per tig
    __shared__ float Bs[32][136];   // [k][n]
    const int tid  = threadIdx.x;
    const int lane = tid & 31;
    const int warp = tid >> 5;
    const int g    = lane >> 2, tig = lane & 3;
    const int warpM = warp >> 1, warpN = warp & 1;
    const int rowBase = blockIdx.x * 128;

    float acc[2][8][4];
    #pragma unroll
    for (int mt = 0; mt < 2; mt++)
        #pragma unroll
        for (int nt = 0; nt < 8; nt++)
            #pragma unroll
            for (int i = 0; i < 4; i++) acc[mt][nt][i] = 0.0f;

    const int aRow = tid >> 1, aK = (tid & 1) * 16;   // A: 2 thr/row, 16 k each
    const int bK = tid >> 3,  bN = (tid & 7) * 16;    // B: 8 thr/row, 16 n each

    for (int k0 = 0; k0 < K; k0 += 32) {
        #pragma unroll
        for (int i = 0; i < 4; i++) {
            float4 v = *(const float4*)&A[(size_t)(rowBase + aRow) * K + (k0 + aK + i * 4)];
            As[aK + i * 4 + 0][aRow] = v.x;
            As[aK + i * 4 + 1][aRow] = v.y;
            As[aK + i * 4 + 2][aRow] = v.z;
            As[aK + i * 4 + 3][aRow] = v.w;
        }
        #pragma unroll
        for (int i = 0; i < 4; i++) {
            *(float4*)&Bs[bK][bN + i * 4] =
                *(const float4*)&B[(size_t)(k0 + bK) * 128 + bN + i * 4];
        }
        __syncthreads();
        #pragma unroll
        for (int kk = 0; kk < 4; kk++) {
            const int kb = kk * 8;
            unsigned ah[2][4], al[2][4];
            #pragma unroll
            for (int mt = 0; mt < 2; mt++) {
                int r0 = warpM * 32 + mt * 16 + g;
                split2(As[kb + tig    ][r0    ], ah[mt][0], al[mt][0]);
                split2(As[kb + tig    ][r0 + 8], ah[mt][1], al[mt][1]);
                split2(As[kb + tig + 4][r0    ], ah[mt][2], al[mt][2]);
                split2(As[kb + tig + 4][r0 + 8], ah[mt][3], al[mt][3]);
            }
            #pragma unroll
            for (int nt = 0; nt < 8; nt++) {
                int c0 = warpN * 64 + nt * 8 + g;
                unsigned bh[2], bl[2];
                split2(Bs[kb + tig    ][c0], bh[0], bl[0]);
                split2(Bs[kb + tig + 4][c0], bh[1], bl[1]);
                #pragma unroll
                for (int mt = 0; mt < 2; mt++) {
                    mma8(acc[mt][nt], ah[mt], bh);   // hi*hi
                    mma8(acc[mt][nt], al[mt], bh);   // lo*hi
                    mma8(acc[mt][nt], ah[mt], bl);   // hi*lo
                }
            }
        }
        __syncthreads();
    }
    #pragma unroll
    for (int mt = 0; mt < 2; mt++) {
        #pragma unroll
        for (int nt = 0; nt < 8; nt++) {
            int r = rowBase + warpM * 32 + mt * 16 + g;
            int c = warpN * 64 + nt * 8 + tig * 2;
            *(float2*)&C[(size_t)r * 128 + c]       = make_float2(acc[mt][nt][0], acc[mt][nt][1]);
            *(float2*)&C[(size_t)(r + 8) * 128 + c] = make_float2(acc[mt][nt][2], acc[mt][nt][3]);
        }
    }
}

__global__ __launch_bounds__(256, 2)
void gemm1_kernel(const float* __restrict__ x, const float* __restrict__ W1) {
    mma_gemm_body<IN_C>(x, W1, g_bufA);
}
__global__ __launch_bounds__(256, 2)
void gemm2_kernel(const float* __restrict__ W2) {
    mma_gemm_body<HID>(g_bufB, W2, g_bufA);
}

// ---------------- aggregation: pull-mode, 1 warp per dst node --------------
__global__ void agg_kernel(const float* __restrict__ bias) {
    int w = (blockIdx.x * blockDim.x + threadIdx.x) >> 5;
    int lane = threadIdx.x & 31;
    if (w >= N_NODES) return;
    const float* __restrict__ h = g_bufA;
    float dv = g_dinv[w];
    float4 sv = *(const float4*)(h + (size_t)w * HID + lane * 4);
    float4 acc = make_float4(dv * sv.x, dv * sv.y, dv * sv.z, dv * sv.w);
    int beg = g_rowptr[w], end = g_rowptr[w + 1];
    for (int e = beg; e < end; e++) {
        int s = g_col[e];
        float ws = g_dinv[s];
        float4 v = *(const float4*)(h + (size_t)s * HID + lane * 4);
        acc.x += ws * v.x; acc.y += ws * v.y;
        acc.z += ws * v.z; acc.w += ws * v.w;
    }
    float4 b = *(const float4*)(bias + lane * 4);
    float4 o;
    o.x = fmaxf(dv * acc.x + b.x, 0.0f);
    o.y = fmaxf(dv * acc.y + b.y, 0.0f);
    o.z = fmaxf(dv * acc.z + b.z, 0.0f);
    o.w = fmaxf(dv * acc.w + b.w, 0.0f);
    *(float4*)(g_bufB + (size_t)w * HID + lane * 4) = o;
}

// ------- layer-2 aggregation with fused mean-pool (no bufB round-trip) -----
__global__ void agg_pool_kernel(const float* __restrict__ bias,
                                const int* __restrict__ bids) {
    int w = (blockIdx.x * blockDim.x + threadIdx.x) >> 5;
    int lane = threadIdx.x & 31;
    if (w >= N_NODES) return;
    const float* __restrict__ h = g_bufA;
    float dv = g_dinv[w];
    float4 sv = *(const float4*)(h + (size_t)w * HID + lane * 4);
    float4 acc = make_float4(dv * sv.x, dv * sv.y, dv * sv.z, dv * sv.w);
    int beg = g_rowptr[w], end = g_rowptr[w + 1];
    for (int e = beg; e < end; e++) {
        int s = g_col[e];
        float ws = g_dinv[s];
        float4 v = *(const float4*)(h + (size_t)s * HID + lane * 4);
        acc.x += ws * v.x; acc.y += ws * v.y;
        acc.z += ws * v.z; acc.w += ws * v.w;
    }
    float4 b = *(const float4*)(bias + lane * 4);
    float4 o;
    o.x = fmaxf(dv * acc.x + b.x, 0.0f);
    o.y = fmaxf(dv * acc.y + b.y, 0.0f);
    o.z = fmaxf(dv * acc.z + b.z, 0.0f);
    o.w = fmaxf(dv * acc.w + b.w, 0.0f);
    unsigned gr = (unsigned)bids[w];
    if (gr >= N_GRAPHS) gr = 0;
    float* p = &g_pool[gr * HID + lane * 4];
    atomicAdd(p + 0, o.x);
    atomicAdd(p + 1, o.y);
    atomicAdd(p + 2, o.z);
    atomicAdd(p + 3, o.w);
    if (lane == 0) atomicAdd(&g_cntg[gr], 1.0f);
}

// ---------------- final linear head: 1 warp per graph ----------------------
__global__ void final_kernel(const float* __restrict__ Wlin,
                             const float* __restrict__ blin,
                             float* __restrict__ out) {
    int g = (blockIdx.x * blockDim.x + threadIdx.x) >> 5;
    int lane = threadIdx.x & 31;
    if (g >= N_GRAPHS) return;
    float inv = 1.0f / fmaxf(g_cntg[g], 1.0f);
    float4 p = *(const float4*)(&g_pool[g * HID + lane * 4]);
    p.x *= inv; p.y *= inv; p.z *= inv; p.w *= inv;
    int c = lane * 4;
    float s0 = p.x * Wlin[c * 2]       + p.y * Wlin[(c + 1) * 2]
             + p.z * Wlin[(c + 2) * 2] + p.w * Wlin[(c + 3) * 2];
    float s1 = p.x * Wlin[c * 2 + 1]       + p.y * Wlin[(c + 1) * 2 + 1]
             + p.z * Wlin[(c + 2) * 2 + 1] + p.w * Wlin[(c + 3) * 2 + 1];
    #pragma unroll
    for (int off = 16; off > 0; off >>= 1) {
        s0 += __shfl_xor_sync(0xFFFFFFFF, s0, off);
        s1 += __shfl_xor_sync(0xFFFFFFFF, s1, off);
    }
    if (lane == 0) {
        out[g * 2 + 0] = s0 + blin[0];
        out[g * 2 + 1] = s1 + blin[1];
    }
}

// ---------------- launch ----------------------------------------------------
extern "C" void kernel_launch(void* const* d_in, const int* in_sizes, int n_in,
                              void* d_out, int out_size) {
    const float* x    = (const float*)d_in[0];
    const int*   edge = (const int*)d_in[1];    // int32
    const int*   bids = (const int*)d_in[2];    // int32
    const float* W1   = (const float*)d_in[3];
    const float* b1   = (const float*)d_in[4];
    const float* W2   = (const float*)d_in[5];
    const float* b2   = (const float*)d_in[6];
    const float* Wlin = (const float*)d_in[7];
    const float* blin = (const float*)d_in[8];
    float*       out  = (float*)d_out;

    init_kernel<<<(N_NODES + 255) / 256, 256>>>();
    count_kernel<<<(N_EDGES + 255) / 256, 256>>>(edge);
    scan_kernel<<<1, 1024>>>();
    fill_kernel<<<(N_EDGES + 255) / 256, 256>>>(edge);

    int gemmGrid = N_NODES / 128;   // 788, exact
    int aggBlocks = (N_NODES * 32 + 255) / 256;

    // layer 1
    gemm1_kernel<<<gemmGrid, 256>>>(x, W1);
    agg_kernel<<<aggBlocks, 256>>>(b1);
    // layer 2 (+ fused mean pool)
    gemm2_kernel<<<gemmGrid, 256>>>(W2);
    agg_pool_kernel<<<aggBlocks, 256>>>(b2, bids);
    // head
    final_kernel<<<(N_GRAPHS * 32 + 255) / 256, 256>>>(Wlin, blin, out);
}